// round 2
// baseline (speedup 1.0000x reference)
#include <cuda_runtime.h>

#define BATCH 1024
#define DIM 1024
#define NUM_SAMPLES 100
#define ETA 0.5f
#define KAPPA 0.1f

// One CTA per batch row. 512 threads stream 100*1024 floats (sum of squares)
// with deep explicit MLP (5 independent LDG.128 per batch, streaming hint),
// plus the two small 1024-float row reductions, then block-reduce + epilogue.
__global__ __launch_bounds__(512, 3) void soliton_kernel(
    const float* __restrict__ residue,
    const float* __restrict__ constraint,
    const float* __restrict__ pert,
    float* __restrict__ out)
{
    const int b   = blockIdx.x;
    const int tid = threadIdx.x;

    // ---- issue small loads FIRST so their latency hides under the big stream ----
    float s_r = 0.0f, s_c = 0.0f;
    float4 rv = make_float4(0.f, 0.f, 0.f, 0.f);
    float4 cv = make_float4(0.f, 0.f, 0.f, 0.f);
    if (tid < DIM / 4) {  // 256 threads, one float4 each
        const float4* __restrict__ r4 =
            reinterpret_cast<const float4*>(residue + (size_t)b * DIM);
        const float4* __restrict__ c4 =
            reinterpret_cast<const float4*>(constraint + (size_t)b * DIM);
        rv = __ldcs(&r4[tid]);
        cv = __ldcs(&c4[tid]);
    }

    // ---- perturbation sum of squares: 102400 floats = 25600 float4 ----
    // Each thread: 50 float4, processed as 10 batches of 5 independent loads.
    const float4* __restrict__ p4 =
        reinterpret_cast<const float4*>(pert + (size_t)b * (NUM_SAMPLES * DIM));

    float a0 = 0.f, a1 = 0.f, a2 = 0.f, a3 = 0.f, a4 = 0.f;
    #pragma unroll 1
    for (int k = 0; k < 10; k++) {
        const int base = tid + k * (5 * 512);
        // 5 independent streaming loads — ptxas front-batches these (MLP=5)
        float4 v0 = __ldcs(&p4[base]);
        float4 v1 = __ldcs(&p4[base + 512]);
        float4 v2 = __ldcs(&p4[base + 2 * 512]);
        float4 v3 = __ldcs(&p4[base + 3 * 512]);
        float4 v4 = __ldcs(&p4[base + 4 * 512]);
        a0 = fmaf(v0.x, v0.x, fmaf(v0.y, v0.y, fmaf(v0.z, v0.z, fmaf(v0.w, v0.w, a0))));
        a1 = fmaf(v1.x, v1.x, fmaf(v1.y, v1.y, fmaf(v1.z, v1.z, fmaf(v1.w, v1.w, a1))));
        a2 = fmaf(v2.x, v2.x, fmaf(v2.y, v2.y, fmaf(v2.z, v2.z, fmaf(v2.w, v2.w, a2))));
        a3 = fmaf(v3.x, v3.x, fmaf(v3.y, v3.y, fmaf(v3.z, v3.z, fmaf(v3.w, v3.w, a3))));
        a4 = fmaf(v4.x, v4.x, fmaf(v4.y, v4.y, fmaf(v4.z, v4.z, fmaf(v4.w, v4.w, a4))));
    }
    float s_p = ((a0 + a1) + (a2 + a3)) + a4;

    // fold the small-tensor squares
    s_r = rv.x * rv.x + rv.y * rv.y + rv.z * rv.z + rv.w * rv.w;
    s_c = cv.x * cv.x + cv.y * cv.y + cv.z * cv.z + cv.w * cv.w;

    // ---- 3-way block reduction: warp shuffle then smem across 16 warps ----
    #pragma unroll
    for (int o = 16; o > 0; o >>= 1) {
        s_p += __shfl_down_sync(0xffffffffu, s_p, o);
        s_r += __shfl_down_sync(0xffffffffu, s_r, o);
        s_c += __shfl_down_sync(0xffffffffu, s_c, o);
    }

    __shared__ float sh_p[16], sh_r[16], sh_c[16];
    const int wid  = tid >> 5;
    const int lane = tid & 31;
    if (lane == 0) { sh_p[wid] = s_p; sh_r[wid] = s_r; sh_c[wid] = s_c; }
    __syncthreads();

    if (wid == 0) {
        s_p = (lane < 16) ? sh_p[lane] : 0.0f;
        s_r = (lane < 16) ? sh_r[lane] : 0.0f;
        s_c = (lane < 16) ? sh_c[lane] : 0.0f;
        #pragma unroll
        for (int o = 8; o > 0; o >>= 1) {
            s_p += __shfl_down_sync(0xffffffffu, s_p, o);
            s_r += __shfl_down_sync(0xffffffffu, s_r, o);
            s_c += __shfl_down_sync(0xffffffffu, s_c, o);
        }
        if (lane == 0) {
            float dispersion = s_p * (1.0f / NUM_SAMPLES);
            float energy = s_r;
            float cscale = sqrtf(s_c);
            float energy_density = energy / (cscale + 1e-8f);
            float localization = (energy > 0.0f)
                                   ? ETA / (energy_density + 1e-8f)
                                   : cscale;
            float ratio = dispersion / (localization + 1e-8f);
            // Output tuple order: is_soliton, dispersion, localization, ratio
            out[b]             = (ratio < KAPPA) ? 1.0f : 0.0f;
            out[BATCH + b]     = dispersion;
            out[2 * BATCH + b] = localization;
            out[3 * BATCH + b] = ratio;
        }
    }
}

extern "C" void kernel_launch(void* const* d_in, const int* in_sizes, int n_in,
                              void* d_out, int out_size) {
    const float* residue    = (const float*)d_in[0];
    const float* constraint = (const float*)d_in[1];
    const float* pert       = (const float*)d_in[2];

    // Robustness: identify the perturbation tensor by size in case of ordering drift.
    for (int i = 0; i < n_in; i++) {
        if (in_sizes[i] == BATCH * NUM_SAMPLES * DIM) {
            pert = (const float*)d_in[i];
        }
    }
    if (pert == (const float*)d_in[0]) {
        residue    = (const float*)d_in[1];
        constraint = (const float*)d_in[2];
    } else if (pert == (const float*)d_in[1]) {
        residue    = (const float*)d_in[0];
        constraint = (const float*)d_in[2];
    }

    float* out = (float*)d_out;
    soliton_kernel<<<BATCH, 512>>>(residue, constraint, pert, out);
}